// round 2
// baseline (speedup 1.0000x reference)
#include <cuda_runtime.h>
#include <math.h>

// Problem constants (fixed by the dataset)
#define NN    100000
#define DK    256
#define NU    256
#define EPSF  1e-5f

// Scratch: h_tan [NN, NU] lives in a device global (no allocs allowed).
__device__ __align__(16) float g_H[(size_t)NN * NU];
__device__ float g_c, g_sc, g_bb;
__device__ __align__(16) float g_bhyp[NU];

// ---------------------------------------------------------------------------
// Setup: c = softplus(c_theta), sqrt_c, b_hyp = exp_map_0(bias), bb = ||b_hyp||^2
// ---------------------------------------------------------------------------
__global__ void setup_kernel(const float* __restrict__ bias,
                             const float* __restrict__ c_theta) {
    __shared__ float red[8];
    __shared__ float s_sc, s_sum;
    int t = threadIdx.x;
    float b = bias[t];
    float v = b * b;
    #pragma unroll
    for (int o = 16; o; o >>= 1) v += __shfl_xor_sync(0xffffffffu, v, o);
    if ((t & 31) == 0) red[t >> 5] = v;
    __syncthreads();
    if (t == 0) {
        float s = 0.f;
        #pragma unroll
        for (int i = 0; i < 8; i++) s += red[i];
        float ct = c_theta[0];
        float c = (ct > 20.f) ? ct : log1pf(expf(ct));
        s_sc = sqrtf(c); s_sum = s;
        g_c = c; g_sc = s_sc;
    }
    __syncthreads();
    float sc = s_sc;
    float S  = s_sum;
    float nb = fmaxf(sqrtf(S), EPSF);
    float fb = tanhf(sc * nb) / (sc * nb);
    g_bhyp[t] = fb * b;
    if (t == 0) g_bb = fb * fb * S;
}

// ---------------------------------------------------------------------------
// Per-row scalars: the whole exp/mobius/project/log chain reduces to
// h_tan = alpha * z + beta * b_hyp  given S1 = sum(z^2), S2 = dot(z, b_hyp).
// ---------------------------------------------------------------------------
__device__ __forceinline__ void row_scalars(float S1, float S2, float c,
                                            float sc, float bb,
                                            float& alpha, float& beta) {
    float nz  = fmaxf(sqrtf(S1), EPSF);
    float t   = tanhf(sc * nz);
    float fz  = t / (sc * nz);             // exp_map factor
    float aa  = fz * fz * S1;              // ||a||^2
    float ab  = fz * S2;                   // <a, b>
    float cA  = 1.f + 2.f * c * ab + c * bb;      // multiplies a
    float cB  = 1.f - c * aa;                     // multiplies b
    float den = 1.f + 2.f * c * ab + c * c * aa * bb;
    float denc = fmaxf(den, EPSF);
    // ||h||^2 analytically (h = (cA*a + cB*b)/denc)
    float hh = (cA * cA * aa + 2.f * cA * cB * ab + cB * cB * bb) / (denc * denc);
    float nraw = sqrtf(hh);
    float nc   = fmaxf(nraw, EPSF);
    float maxn = (1.f - EPSF) / sc;
    float scale = (nc > maxn) ? (maxn / nc) : 1.f;
    float ny  = fmaxf(nraw * scale, EPSF);
    float arg = fminf(sc * ny, 1.f - EPSF);
    float L   = atanhf(arg) / (sc * ny);   // log_map factor
    float g   = L * scale / denc;
    alpha = g * cA * fz;
    beta  = g * cB;
}

// ---------------------------------------------------------------------------
// Fused SGEMM (z = x @ W) + hyperbolic epilogue -> g_H = h_tan
// Tile: BM=64 rows x full 256 cols, BK=32. 256 threads.
// Warp w owns rows [w*8, w*8+8); lane owns cols {4*lane..+3} U {128+4*lane..+3}.
// ---------------------------------------------------------------------------
#define BM 64
#define BK 32

__global__ __launch_bounds__(256)
void gemm_htan_kernel(const float* __restrict__ x, const float* __restrict__ Wk) {
    __shared__ float As[BM][BK + 4];   // [m][k], row padded
    __shared__ float Bs[BK][NU];       // [k][n]

    const int tid = threadIdx.x;
    const int rg  = tid >> 5;          // warp id 0..7 -> row group
    const int cg  = tid & 31;          // lane -> col group
    const int m0  = blockIdx.x * BM;

    float acc[8][8];
    #pragma unroll
    for (int i = 0; i < 8; i++)
        #pragma unroll
        for (int j = 0; j < 8; j++) acc[i][j] = 0.f;

    for (int kt = 0; kt < DK; kt += BK) {
        // Load A tile: 64x32 floats, 2 float4 per thread, coalesced
        #pragma unroll
        for (int s = 0; s < 2; s++) {
            int idx4 = tid + s * 256;          // 0..511 float4s
            int m    = idx4 >> 3;              // 0..63
            int kkb  = (idx4 & 7) * 4;         // 0..28
            int gr   = m0 + m;
            float4 v = make_float4(0.f, 0.f, 0.f, 0.f);
            if (gr < NN)
                v = *(const float4*)(x + (size_t)gr * DK + kt + kkb);
            *(float4*)&As[m][kkb] = v;
        }
        // Load B tile: 32x256 floats, 8 float4 per thread, coalesced
        #pragma unroll
        for (int s = 0; s < 8; s++) {
            int idx4 = tid + s * 256;          // 0..2047
            int kk   = idx4 >> 6;              // 0..31
            int n    = (idx4 & 63) * 4;
            *(float4*)&Bs[kk][n] = *(const float4*)(Wk + (size_t)(kt + kk) * NU + n);
        }
        __syncthreads();

        #pragma unroll
        for (int kk = 0; kk < BK; kk++) {
            float a[8], b[8];
            #pragma unroll
            for (int i = 0; i < 8; i++) a[i] = As[rg * 8 + i][kk];  // broadcast
            *(float4*)(b)     = *(float4*)&Bs[kk][cg * 4];          // conflict-free
            *(float4*)(b + 4) = *(float4*)&Bs[kk][128 + cg * 4];
            #pragma unroll
            for (int i = 0; i < 8; i++)
                #pragma unroll
                for (int j = 0; j < 8; j++)
                    acc[i][j] = fmaf(a[i], b[j], acc[i][j]);
        }
        __syncthreads();
    }

    // ---- Epilogue: per-row S1, S2 -> alpha/beta -> h_tan write ----
    const float c  = g_c;
    const float sc = g_sc;
    const float bb = g_bb;
    float bv[8];
    *(float4*)(bv)     = *(const float4*)&g_bhyp[cg * 4];
    *(float4*)(bv + 4) = *(const float4*)&g_bhyp[128 + cg * 4];

    float S1[8], S2[8];
    #pragma unroll
    for (int i = 0; i < 8; i++) {
        float s1 = 0.f, s2 = 0.f;
        #pragma unroll
        for (int j = 0; j < 8; j++) {
            s1 = fmaf(acc[i][j], acc[i][j], s1);
            s2 = fmaf(acc[i][j], bv[j], s2);
        }
        S1[i] = s1; S2[i] = s2;
    }
    #pragma unroll
    for (int o = 16; o; o >>= 1) {
        #pragma unroll
        for (int i = 0; i < 8; i++) {
            S1[i] += __shfl_xor_sync(0xffffffffu, S1[i], o);
            S2[i] += __shfl_xor_sync(0xffffffffu, S2[i], o);
        }
    }

    #pragma unroll
    for (int i = 0; i < 8; i++) {
        int row = m0 + rg * 8 + i;
        if (row >= NN) continue;
        float alpha, beta;
        row_scalars(S1[i], S2[i], c, sc, bb, alpha, beta);
        float4 o0, o1;
        o0.x = fmaf(alpha, acc[i][0], beta * bv[0]);
        o0.y = fmaf(alpha, acc[i][1], beta * bv[1]);
        o0.z = fmaf(alpha, acc[i][2], beta * bv[2]);
        o0.w = fmaf(alpha, acc[i][3], beta * bv[3]);
        o1.x = fmaf(alpha, acc[i][4], beta * bv[4]);
        o1.y = fmaf(alpha, acc[i][5], beta * bv[5]);
        o1.z = fmaf(alpha, acc[i][6], beta * bv[6]);
        o1.w = fmaf(alpha, acc[i][7], beta * bv[7]);
        *(float4*)(g_H + (size_t)row * NU + cg * 4)       = o0;
        *(float4*)(g_H + (size_t)row * NU + 128 + cg * 4) = o1;
    }
}

// ---------------------------------------------------------------------------
// Edge scatter: one warp per edge. out[row] += w * H[col]  (256 floats)
// Vectorized reduction atomics (sm_90+): red.global.add.v4.f32
// ---------------------------------------------------------------------------
__global__ __launch_bounds__(256)
void scatter_kernel(const int* __restrict__ rows, const int* __restrict__ cols,
                    const float* __restrict__ vals, float* __restrict__ out,
                    int E) {
    const int lane    = threadIdx.x & 31;
    const int warps   = (int)((gridDim.x * blockDim.x) >> 5);
    int gw = (int)((blockIdx.x * (unsigned)blockDim.x + threadIdx.x) >> 5);

    for (; gw < E; gw += warps) {
        int r   = __ldg(rows + gw);
        int s   = __ldg(cols + gw);
        float w = __ldg(vals + gw);

        const float4* src = (const float4*)(g_H + (size_t)s * NU);
        float4 v0 = __ldg(src + lane);
        float4 v1 = __ldg(src + 32 + lane);

        float* dst = out + (size_t)r * NU;
        asm volatile("red.global.add.v4.f32 [%0], {%1,%2,%3,%4};"
                     :: "l"(dst + lane * 4),
                        "f"(w * v0.x), "f"(w * v0.y), "f"(w * v0.z), "f"(w * v0.w)
                     : "memory");
        asm volatile("red.global.add.v4.f32 [%0], {%1,%2,%3,%4};"
                     :: "l"(dst + 128 + lane * 4),
                        "f"(w * v1.x), "f"(w * v1.y), "f"(w * v1.z), "f"(w * v1.w)
                     : "memory");
    }
}

// ---------------------------------------------------------------------------
// In-place ReLU on the accumulated output
// ---------------------------------------------------------------------------
__global__ __launch_bounds__(256)
void relu_kernel(float4* __restrict__ out, int n4) {
    int i = blockIdx.x * blockDim.x + threadIdx.x;
    if (i < n4) {
        float4 v = out[i];
        v.x = fmaxf(v.x, 0.f);
        v.y = fmaxf(v.y, 0.f);
        v.z = fmaxf(v.z, 0.f);
        v.w = fmaxf(v.w, 0.f);
        out[i] = v;
    }
}

// ---------------------------------------------------------------------------
// inputs: 0=x, 1=adj_rows, 2=adj_cols, 3=adj_vals, 4=kernel, 5=bias, 6=c_theta
// ---------------------------------------------------------------------------
extern "C" void kernel_launch(void* const* d_in, const int* in_sizes, int n_in,
                              void* d_out, int out_size) {
    const float* x     = (const float*)d_in[0];
    const int*   arows = (const int*)  d_in[1];
    const int*   acols = (const int*)  d_in[2];
    const float* avals = (const float*)d_in[3];
    const float* Wk    = (const float*)d_in[4];
    const float* bias  = (const float*)d_in[5];
    const float* ct    = (const float*)d_in[6];
    float* out = (float*)d_out;
    const int E = in_sizes[1];

    setup_kernel<<<1, NU>>>(bias, ct);
    cudaMemsetAsync(out, 0, (size_t)out_size * sizeof(float));
    gemm_htan_kernel<<<(NN + BM - 1) / BM, 256>>>(x, Wk);
    int nblocks = (E + 7) / 8;   // 8 warps (edges) per 256-thread block
    scatter_kernel<<<nblocks, 256>>>(arows, acols, avals, out, E);
    relu_kernel<<<(NN * NU / 4 + 255) / 256, 256>>>((float4*)out, NN * NU / 4);
}

// round 4
// speedup vs baseline: 1.7254x; 1.7254x over previous
#include <cuda_runtime.h>
#include <math.h>

// Problem constants (fixed by the dataset)
#define NN    100000
#define NE    3200000
#define DK    256
#define NU    256
#define EPSF  1e-5f

// Scratch (device globals; no allocs allowed)
__device__ __align__(16) float  g_H[(size_t)NN * NU];     // h_tan
__device__ float g_c, g_sc, g_bb;
__device__ __align__(16) float  g_bhyp[NU];
__device__ int    g_cnt[NN];        // per-row edge counts (zeroed each call)
__device__ int    g_off[NN + 1];    // CSR row offsets
__device__ int    g_cur[NN];        // build cursors
__device__ __align__(8) float2 g_edge[NE];   // (col as int bits, weight)

// ---------------------------------------------------------------------------
// Zero the histogram counters (avoids host-side symbol-address + memset)
// ---------------------------------------------------------------------------
__global__ __launch_bounds__(256)
void zero_cnt_kernel() {
    int i = blockIdx.x * blockDim.x + threadIdx.x;
    if (i < NN) g_cnt[i] = 0;
}

// ---------------------------------------------------------------------------
// Setup: c = softplus(c_theta), sqrt_c, b_hyp = exp_map_0(bias), bb = ||b_hyp||^2
// ---------------------------------------------------------------------------
__global__ void setup_kernel(const float* __restrict__ bias,
                             const float* __restrict__ c_theta) {
    __shared__ float red[8];
    __shared__ float s_sc, s_sum;
    int t = threadIdx.x;
    float b = bias[t];
    float v = b * b;
    #pragma unroll
    for (int o = 16; o; o >>= 1) v += __shfl_xor_sync(0xffffffffu, v, o);
    if ((t & 31) == 0) red[t >> 5] = v;
    __syncthreads();
    if (t == 0) {
        float s = 0.f;
        #pragma unroll
        for (int i = 0; i < 8; i++) s += red[i];
        float ct = c_theta[0];
        float c = (ct > 20.f) ? ct : log1pf(expf(ct));
        s_sc = sqrtf(c); s_sum = s;
        g_c = c; g_sc = s_sc;
    }
    __syncthreads();
    float sc = s_sc;
    float S  = s_sum;
    float nb = fmaxf(sqrtf(S), EPSF);
    float fb = tanhf(sc * nb) / (sc * nb);
    g_bhyp[t] = fb * b;
    if (t == 0) g_bb = fb * fb * S;
}

// ---------------------------------------------------------------------------
// Per-row scalars: exp/mobius/project/log chain collapses to
// h_tan = alpha * z + beta * b_hyp  given S1 = sum(z^2), S2 = dot(z, b_hyp).
// ---------------------------------------------------------------------------
__device__ __forceinline__ void row_scalars(float S1, float S2, float c,
                                            float sc, float bb,
                                            float& alpha, float& beta) {
    float nz  = fmaxf(sqrtf(S1), EPSF);
    float t   = tanhf(sc * nz);
    float fz  = t / (sc * nz);             // exp_map factor
    float aa  = fz * fz * S1;              // ||a||^2
    float ab  = fz * S2;                   // <a, b>
    float cA  = 1.f + 2.f * c * ab + c * bb;
    float cB  = 1.f - c * aa;
    float den = 1.f + 2.f * c * ab + c * c * aa * bb;
    float denc = fmaxf(den, EPSF);
    float hh = (cA * cA * aa + 2.f * cA * cB * ab + cB * cB * bb) / (denc * denc);
    float nraw = sqrtf(hh);
    float nc   = fmaxf(nraw, EPSF);
    float maxn = (1.f - EPSF) / sc;
    float scale = (nc > maxn) ? (maxn / nc) : 1.f;
    float ny  = fmaxf(nraw * scale, EPSF);
    float arg = fminf(sc * ny, 1.f - EPSF);
    float L   = atanhf(arg) / (sc * ny);   // log_map factor
    float g   = L * scale / denc;
    alpha = g * cA * fz;
    beta  = g * cB;
}

// ---------------------------------------------------------------------------
// Fused SGEMM (z = x @ W) + hyperbolic epilogue -> g_H = h_tan
// ---------------------------------------------------------------------------
#define BM 64
#define BK 32

__global__ __launch_bounds__(256)
void gemm_htan_kernel(const float* __restrict__ x, const float* __restrict__ Wk) {
    __shared__ float As[BM][BK + 4];
    __shared__ float Bs[BK][NU];

    const int tid = threadIdx.x;
    const int rg  = tid >> 5;
    const int cg  = tid & 31;
    const int m0  = blockIdx.x * BM;

    float acc[8][8];
    #pragma unroll
    for (int i = 0; i < 8; i++)
        #pragma unroll
        for (int j = 0; j < 8; j++) acc[i][j] = 0.f;

    for (int kt = 0; kt < DK; kt += BK) {
        #pragma unroll
        for (int s = 0; s < 2; s++) {
            int idx4 = tid + s * 256;
            int m    = idx4 >> 3;
            int kkb  = (idx4 & 7) * 4;
            int gr   = m0 + m;
            float4 v = make_float4(0.f, 0.f, 0.f, 0.f);
            if (gr < NN)
                v = *(const float4*)(x + (size_t)gr * DK + kt + kkb);
            *(float4*)&As[m][kkb] = v;
        }
        #pragma unroll
        for (int s = 0; s < 8; s++) {
            int idx4 = tid + s * 256;
            int kk   = idx4 >> 6;
            int n    = (idx4 & 63) * 4;
            *(float4*)&Bs[kk][n] = *(const float4*)(Wk + (size_t)(kt + kk) * NU + n);
        }
        __syncthreads();

        #pragma unroll
        for (int kk = 0; kk < BK; kk++) {
            float a[8], b[8];
            #pragma unroll
            for (int i = 0; i < 8; i++) a[i] = As[rg * 8 + i][kk];
            *(float4*)(b)     = *(float4*)&Bs[kk][cg * 4];
            *(float4*)(b + 4) = *(float4*)&Bs[kk][128 + cg * 4];
            #pragma unroll
            for (int i = 0; i < 8; i++)
                #pragma unroll
                for (int j = 0; j < 8; j++)
                    acc[i][j] = fmaf(a[i], b[j], acc[i][j]);
        }
        __syncthreads();
    }

    const float c  = g_c;
    const float sc = g_sc;
    const float bb = g_bb;
    float bv[8];
    *(float4*)(bv)     = *(const float4*)&g_bhyp[cg * 4];
    *(float4*)(bv + 4) = *(const float4*)&g_bhyp[128 + cg * 4];

    float S1[8], S2[8];
    #pragma unroll
    for (int i = 0; i < 8; i++) {
        float s1 = 0.f, s2 = 0.f;
        #pragma unroll
        for (int j = 0; j < 8; j++) {
            s1 = fmaf(acc[i][j], acc[i][j], s1);
            s2 = fmaf(acc[i][j], bv[j], s2);
        }
        S1[i] = s1; S2[i] = s2;
    }
    #pragma unroll
    for (int o = 16; o; o >>= 1) {
        #pragma unroll
        for (int i = 0; i < 8; i++) {
            S1[i] += __shfl_xor_sync(0xffffffffu, S1[i], o);
            S2[i] += __shfl_xor_sync(0xffffffffu, S2[i], o);
        }
    }

    #pragma unroll
    for (int i = 0; i < 8; i++) {
        int row = m0 + rg * 8 + i;
        if (row >= NN) continue;
        float alpha, beta;
        row_scalars(S1[i], S2[i], c, sc, bb, alpha, beta);
        float4 o0, o1;
        o0.x = fmaf(alpha, acc[i][0], beta * bv[0]);
        o0.y = fmaf(alpha, acc[i][1], beta * bv[1]);
        o0.z = fmaf(alpha, acc[i][2], beta * bv[2]);
        o0.w = fmaf(alpha, acc[i][3], beta * bv[3]);
        o1.x = fmaf(alpha, acc[i][4], beta * bv[4]);
        o1.y = fmaf(alpha, acc[i][5], beta * bv[5]);
        o1.z = fmaf(alpha, acc[i][6], beta * bv[6]);
        o1.w = fmaf(alpha, acc[i][7], beta * bv[7]);
        *(float4*)(g_H + (size_t)row * NU + cg * 4)       = o0;
        *(float4*)(g_H + (size_t)row * NU + 128 + cg * 4) = o1;
    }
}

// ---------------------------------------------------------------------------
// CSR build phase 1: histogram of destination rows
// ---------------------------------------------------------------------------
__global__ __launch_bounds__(256)
void hist_kernel(const int* __restrict__ rows, int E) {
    int i = blockIdx.x * blockDim.x + threadIdx.x;
    if (i < E) atomicAdd(&g_cnt[__ldg(rows + i)], 1);
}

// ---------------------------------------------------------------------------
// CSR build phase 2: exclusive scan of counts (single 1024-thread block)
// ---------------------------------------------------------------------------
__global__ __launch_bounds__(1024)
void scan_kernel(int E) {
    __shared__ int wsum[32];
    __shared__ int s_run;
    const int tid = threadIdx.x, lane = tid & 31, wid = tid >> 5;
    if (tid == 0) s_run = 0;
    __syncthreads();
    for (int base = 0; base < NN; base += 1024) {
        int i = base + tid;
        int v = (i < NN) ? g_cnt[i] : 0;
        int x = v;
        #pragma unroll
        for (int o = 1; o < 32; o <<= 1) {
            int y = __shfl_up_sync(0xffffffffu, x, o);
            if (lane >= o) x += y;
        }
        if (lane == 31) wsum[wid] = x;
        __syncthreads();
        if (wid == 0) {
            int s = wsum[lane];
            #pragma unroll
            for (int o = 1; o < 32; o <<= 1) {
                int y = __shfl_up_sync(0xffffffffu, s, o);
                if (lane >= o) s += y;
            }
            wsum[lane] = s;
        }
        __syncthreads();
        int run  = s_run;
        int excl = x - v + ((wid > 0) ? wsum[wid - 1] : 0);
        if (i < NN) { g_off[i] = run + excl; g_cur[i] = run + excl; }
        __syncthreads();
        if (tid == 1023) s_run = run + wsum[31];
        __syncthreads();
    }
    if (tid == 0) g_off[NN] = E;
}

// ---------------------------------------------------------------------------
// CSR build phase 3: permute edges into row-sorted order
// ---------------------------------------------------------------------------
__global__ __launch_bounds__(256)
void build_kernel(const int* __restrict__ rows, const int* __restrict__ cols,
                  const float* __restrict__ vals, int E) {
    int i = blockIdx.x * blockDim.x + threadIdx.x;
    if (i >= E) return;
    int r = __ldg(rows + i);
    int p = atomicAdd(&g_cur[r], 1);
    g_edge[p] = make_float2(__int_as_float(__ldg(cols + i)), __ldg(vals + i));
}

// ---------------------------------------------------------------------------
// SpMM: one warp per destination row. Accumulate in registers, no atomics,
// fused ReLU, streaming stores (keep H resident in L2).
// ---------------------------------------------------------------------------
__global__ __launch_bounds__(256)
void spmm_kernel(float* __restrict__ out) {
    const int r    = (int)((blockIdx.x * 256u + threadIdx.x) >> 5);
    const int lane = threadIdx.x & 31;
    if (r >= NN) return;
    const int e0 = __ldg(&g_off[r]);
    const int e1 = __ldg(&g_off[r + 1]);

    float acc[8];
    #pragma unroll
    for (int i = 0; i < 8; i++) acc[i] = 0.f;

    int e = e0;
    for (; e + 32 <= e1; e += 32) {
        float2 ed = g_edge[e + lane];
        int   mc  = __float_as_int(ed.x);
        float mw  = ed.y;
        #pragma unroll 4
        for (int j = 0; j < 32; j++) {
            int   col = __shfl_sync(0xffffffffu, mc, j);
            float w   = __shfl_sync(0xffffffffu, mw, j);
            const float4* src = (const float4*)(g_H + (size_t)col * NU);
            float4 v0 = __ldg(src + lane);
            float4 v1 = __ldg(src + 32 + lane);
            acc[0] = fmaf(w, v0.x, acc[0]);
            acc[1] = fmaf(w, v0.y, acc[1]);
            acc[2] = fmaf(w, v0.z, acc[2]);
            acc[3] = fmaf(w, v0.w, acc[3]);
            acc[4] = fmaf(w, v1.x, acc[4]);
            acc[5] = fmaf(w, v1.y, acc[5]);
            acc[6] = fmaf(w, v1.z, acc[6]);
            acc[7] = fmaf(w, v1.w, acc[7]);
        }
    }
    int rem = e1 - e;
    if (rem > 0) {
        float2 ed = (lane < rem) ? g_edge[e + lane] : make_float2(0.f, 0.f);
        int   mc  = __float_as_int(ed.x);
        float mw  = ed.y;
        for (int j = 0; j < rem; j++) {
            int   col = __shfl_sync(0xffffffffu, mc, j);
            float w   = __shfl_sync(0xffffffffu, mw, j);
            const float4* src = (const float4*)(g_H + (size_t)col * NU);
            float4 v0 = __ldg(src + lane);
            float4 v1 = __ldg(src + 32 + lane);
            acc[0] = fmaf(w, v0.x, acc[0]);
            acc[1] = fmaf(w, v0.y, acc[1]);
            acc[2] = fmaf(w, v0.z, acc[2]);
            acc[3] = fmaf(w, v0.w, acc[3]);
            acc[4] = fmaf(w, v1.x, acc[4]);
            acc[5] = fmaf(w, v1.y, acc[5]);
            acc[6] = fmaf(w, v1.z, acc[6]);
            acc[7] = fmaf(w, v1.w, acc[7]);
        }
    }

    float4 o0, o1;
    o0.x = fmaxf(acc[0], 0.f); o0.y = fmaxf(acc[1], 0.f);
    o0.z = fmaxf(acc[2], 0.f); o0.w = fmaxf(acc[3], 0.f);
    o1.x = fmaxf(acc[4], 0.f); o1.y = fmaxf(acc[5], 0.f);
    o1.z = fmaxf(acc[6], 0.f); o1.w = fmaxf(acc[7], 0.f);
    float4* dst = (float4*)(out + (size_t)r * NU);
    __stcs(dst + lane,      o0);
    __stcs(dst + 32 + lane, o1);
}

// ---------------------------------------------------------------------------
// inputs: 0=x, 1=adj_rows, 2=adj_cols, 3=adj_vals, 4=kernel, 5=bias, 6=c_theta
// ---------------------------------------------------------------------------
extern "C" void kernel_launch(void* const* d_in, const int* in_sizes, int n_in,
                              void* d_out, int out_size) {
    const float* x     = (const float*)d_in[0];
    const int*   arows = (const int*)  d_in[1];
    const int*   acols = (const int*)  d_in[2];
    const float* avals = (const float*)d_in[3];
    const float* Wk    = (const float*)d_in[4];
    const float* bias  = (const float*)d_in[5];
    const float* ct    = (const float*)d_in[6];
    float* out = (float*)d_out;
    const int E = in_sizes[1];

    setup_kernel<<<1, NU>>>(bias, ct);
    zero_cnt_kernel<<<(NN + 255) / 256, 256>>>();
    hist_kernel<<<(E + 255) / 256, 256>>>(arows, E);
    scan_kernel<<<1, 1024>>>(E);
    build_kernel<<<(E + 255) / 256, 256>>>(arows, acols, avals, E);
    gemm_htan_kernel<<<(NN + BM - 1) / BM, 256>>>(x, Wk);
    spmm_kernel<<<(NN * 32 + 255) / 256, 256>>>(out);
}